// round 2
// baseline (speedup 1.0000x reference)
#include <cuda_runtime.h>
#include <cstdint>

#define NNODES 100000
#define NEDGES 1600000
#define IN_C 64
#define HID 128
#define OUT_C 64
#define NB 16            // nodes per MLP tile
#define MLP_BLOCKS 296

// Scratch (static device arrays; heap alloc is forbidden)
__device__ __align__(16) float g_h2[(size_t)NNODES * OUT_C];   // 25.6 MB
__device__ float g_deg[NNODES];
__device__ float g_dinv[NNODES];
__device__ int   g_stride;   // 1 if edge_index is int32, 2 if int64 (low word)

// ---------------------------------------------------------------------------
// Detect index width: int64 node-ids < 2^31 have zero high words, so when the
// buffer is int64, int32 view positions 1,3,5,... are all zero. Genuine int32
// indices are uniform in [0,1e5) -> 64 consecutive zeros is impossible.
// ---------------------------------------------------------------------------
__global__ void k_detect(const int* __restrict__ ei) {
    int allzero = 1;
    for (int i = 1; i < 128; i += 2) allzero &= (ei[i] == 0);
    g_stride = allzero ? 2 : 1;
}

// ---------------------------------------------------------------------------
// Degree / normalization
// ---------------------------------------------------------------------------
__global__ void k_deg_init() {
    int i = blockIdx.x * blockDim.x + threadIdx.x;
    if (i < NNODES) g_deg[i] = 1.0f;   // self-loop contributes 1
}

__global__ void k_deg_count(const int* __restrict__ ei) {
    int e = blockIdx.x * blockDim.x + threadIdx.x;
    if (e < NEDGES) {
        const int st = g_stride;
        int d = ei[(size_t)NEDGES * st + (size_t)e * st];   // dst half
        if (d >= 0 && d < NNODES) atomicAdd(&g_deg[d], 1.0f);
    }
}

__global__ void k_dinv() {
    int i = blockIdx.x * blockDim.x + threadIdx.x;
    if (i < NNODES) g_dinv[i] = rsqrtf(g_deg[i]);  // deg >= 1 always
}

// ---------------------------------------------------------------------------
// Fused MLP: h2 = relu(X@W1+b1) @ W2 ; also initializes
//   out[n] = dinv[n]^2 * h2[n] + b2   (self-loop term + bias)
// ---------------------------------------------------------------------------
__global__ __launch_bounds__(256) void k_mlp(
    const float* __restrict__ X, const float* __restrict__ W1,
    const float* __restrict__ b1, const float* __restrict__ W2,
    const float* __restrict__ b2, float* __restrict__ out)
{
    extern __shared__ float sm[];
    float* sW1 = sm;                    // IN_C*HID  = 8192
    float* sW2 = sW1 + IN_C * HID;      // HID*OUT_C = 8192
    float* sb1 = sW2 + HID * OUT_C;     // 128
    float* sb2 = sb1 + HID;             // 64
    float* sX  = sb2 + OUT_C;           // NB*IN_C  = 1024
    float* sH  = sX + NB * IN_C;        // NB*HID   = 2048

    const int t = threadIdx.x;

    for (int i = t; i < IN_C * HID; i += 256)  sW1[i] = W1[i];
    for (int i = t; i < HID * OUT_C; i += 256) sW2[i] = W2[i];
    if (t < HID)   sb1[t] = b1[t];
    if (t < OUT_C) sb2[t] = b2[t];

    const int col = t & 127;          // phase-1 output column
    const int ng  = t >> 7;           // 0..1
    const int j   = t & 63;           // phase-2 output column
    const int ng4 = t >> 6;           // 0..3

    const int ntiles = (NNODES + NB - 1) / NB;
    for (int tile = blockIdx.x; tile < ntiles; tile += gridDim.x) {
        const int base = tile * NB;

        __syncthreads();   // prior iteration done with sX/sH
        for (int i = t; i < NB * IN_C; i += 256) {
            int n = i >> 6, c = i & 63;
            int gn = base + n;
            sX[i] = (gn < NNODES) ? X[(size_t)gn * IN_C + c] : 0.0f;
        }
        __syncthreads();

        // Phase 1: h = relu(X@W1 + b1). 2 nodes per thread.
        for (int nb = 0; nb < NB; nb += 4) {
            const int n0 = nb + ng * 2;
            const int n1 = n0 + 1;
            float a0 = sb1[col], a1 = sb1[col];
            const float* x0 = &sX[n0 * IN_C];
            const float* x1 = &sX[n1 * IN_C];
            #pragma unroll
            for (int k = 0; k < IN_C; k++) {
                float w = sW1[k * HID + col];
                a0 = fmaf(x0[k], w, a0);
                a1 = fmaf(x1[k], w, a1);
            }
            sH[n0 * HID + col] = fmaxf(a0, 0.0f);
            sH[n1 * HID + col] = fmaxf(a1, 0.0f);
        }
        __syncthreads();

        // Phase 2: h2 = h @ W2. 2 nodes per thread.
        for (int nb = 0; nb < NB; nb += 8) {
            const int n0 = nb + ng4 * 2;
            const int n1 = n0 + 1;
            float a0 = 0.0f, a1 = 0.0f;
            const float* h0 = &sH[n0 * HID];
            const float* h1 = &sH[n1 * HID];
            #pragma unroll
            for (int k = 0; k < HID; k++) {
                float w = sW2[k * OUT_C + j];
                a0 = fmaf(h0[k], w, a0);
                a1 = fmaf(h1[k], w, a1);
            }
            const int gn0 = base + n0, gn1 = base + n1;
            if (gn0 < NNODES) {
                g_h2[(size_t)gn0 * OUT_C + j] = a0;
                float di = g_dinv[gn0];
                out[(size_t)gn0 * OUT_C + j] = di * di * a0 + sb2[j];
            }
            if (gn1 < NNODES) {
                g_h2[(size_t)gn1 * OUT_C + j] = a1;
                float di = g_dinv[gn1];
                out[(size_t)gn1 * OUT_C + j] = di * di * a1 + sb2[j];
            }
        }
    }
}

// ---------------------------------------------------------------------------
// Edge scatter: out[dst] += dinv[src]*dinv[dst] * h2[src]
// 16 threads per edge, one float4 chunk each; red.v4 quarters LTS atomic ops.
// ---------------------------------------------------------------------------
__global__ __launch_bounds__(256) void k_edge(
    const int* __restrict__ ei, float* __restrict__ out)
{
    const long long g = (long long)blockIdx.x * blockDim.x + threadIdx.x;
    const int e = (int)(g >> 4);
    if (e >= NEDGES) return;
    const int c = ((int)g & 15) << 2;

    const int st = g_stride;
    const int s = ei[(size_t)e * st];
    const int d = ei[(size_t)NEDGES * st + (size_t)e * st];
    if ((unsigned)s >= NNODES || (unsigned)d >= NNODES) return;

    const float norm = g_dinv[s] * g_dinv[d];

    const float4 v = *reinterpret_cast<const float4*>(&g_h2[(size_t)s * OUT_C + c]);
    float* p = &out[(size_t)d * OUT_C + c];
    asm volatile("red.global.add.v4.f32 [%0], {%1, %2, %3, %4};"
                 :: "l"(p),
                    "f"(v.x * norm), "f"(v.y * norm),
                    "f"(v.z * norm), "f"(v.w * norm)
                 : "memory");
}

// ---------------------------------------------------------------------------
extern "C" void kernel_launch(void* const* d_in, const int* in_sizes, int n_in,
                              void* d_out, int out_size)
{
    const float* X   = (const float*)d_in[0];
    const int*   ei  = (const int*)d_in[1];   // width auto-detected on device
    const float* W1  = (const float*)d_in[2];
    const float* b1  = (const float*)d_in[3];
    const float* W2  = (const float*)d_in[4];
    const float* b2  = (const float*)d_in[5];
    float*       out = (float*)d_out;

    const int smem_bytes = (IN_C*HID + HID*OUT_C + HID + OUT_C + NB*IN_C + NB*HID) * 4;
    static int attr_done = 0;
    if (!attr_done) {
        cudaFuncSetAttribute(k_mlp, cudaFuncAttributeMaxDynamicSharedMemorySize, smem_bytes);
        attr_done = 1;
    }

    k_detect   <<<1, 1>>>(ei);
    k_deg_init <<<(NNODES + 255) / 256, 256>>>();
    k_deg_count<<<(NEDGES + 255) / 256, 256>>>(ei);
    k_dinv     <<<(NNODES + 255) / 256, 256>>>();
    k_mlp      <<<MLP_BLOCKS, 256, smem_bytes>>>(X, W1, b1, W2, b2, out);

    const long long ethreads = (long long)NEDGES * 16;
    k_edge     <<<(int)((ethreads + 255) / 256), 256>>>(ei, out);
}

// round 3
// speedup vs baseline: 1.7453x; 1.7453x over previous
#include <cuda_runtime.h>
#include <cstdint>

#define NNODES 100000
#define NEDGES 1600000
#define IN_C 64
#define HID 128
#define OUT_C 64
#define NB 32            // nodes per MLP tile (100000 % 32 == 0)
#define MLP_BLOCKS 296
#define SCAN_BLK 1024
#define SCAN_NB ((NNODES + SCAN_BLK - 1) / SCAN_BLK)   // 98

// Scratch (static device arrays; heap alloc is forbidden)
__device__ __align__(16) float g_h2s[(size_t)NNODES * OUT_C]; // dinv[n]*h2[n], 25.6 MB
__device__ float g_dinv[NNODES];
__device__ int   g_degi[NNODES];     // in-degree (edges only)
__device__ int   g_off[NNODES];      // CSR offsets (exclusive scan of degi)
__device__ int   g_cur[NNODES];      // scatter cursors
__device__ int   g_esrc[NEDGES];     // CSR: src node per slot, grouped by dst
__device__ int   g_part[SCAN_NB];    // scan partials
__device__ int   g_part2[SCAN_NB];
__device__ int   g_stride;           // 1 = int32 edge_index, 2 = int64 (low word)

// ---------------------------------------------------------------------------
// Index width detection: if buffer is int64 (ids < 2^31), int32 view positions
// 1,3,...,63 (high words of first 32 entries) are all zero. Genuine int32 ids
// are uniform in [0,1e5): P(32 zeros) ~ 1e-160.
// ---------------------------------------------------------------------------
__global__ void k_detect(const int* __restrict__ ei) {
    int lane = threadIdx.x;
    int z = (ei[2 * lane + 1] == 0);
    unsigned m = __ballot_sync(0xFFFFFFFFu, z);
    if (lane == 0) g_stride = (m == 0xFFFFFFFFu) ? 2 : 1;
}

// ---------------------------------------------------------------------------
// Degree histogram (int) and dinv
// ---------------------------------------------------------------------------
__global__ void k_deg_init() {
    int i = blockIdx.x * blockDim.x + threadIdx.x;
    if (i < NNODES) g_degi[i] = 0;
}

__global__ void k_deg_count(const int* __restrict__ ei) {
    int e = blockIdx.x * blockDim.x + threadIdx.x;
    if (e < NEDGES) {
        const int st = g_stride;
        int d = ei[(size_t)NEDGES * st + (size_t)e * st];
        if ((unsigned)d < NNODES) atomicAdd(&g_degi[d], 1);
    }
}

__global__ void k_dinv() {
    int i = blockIdx.x * blockDim.x + threadIdx.x;
    if (i < NNODES) g_dinv[i] = rsqrtf((float)(g_degi[i] + 1));  // +1 self-loop
}

// ---------------------------------------------------------------------------
// Two-level exclusive scan of g_degi -> g_off ; then cursors
// ---------------------------------------------------------------------------
__global__ __launch_bounds__(SCAN_BLK) void k_scan1() {
    __shared__ int s[SCAN_BLK];
    const int t = threadIdx.x;
    const int i = blockIdx.x * SCAN_BLK + t;
    int v = (i < NNODES) ? g_degi[i] : 0;
    s[t] = v;
    __syncthreads();
    #pragma unroll
    for (int off = 1; off < SCAN_BLK; off <<= 1) {
        int add = (t >= off) ? s[t - off] : 0;
        __syncthreads();
        s[t] += add;
        __syncthreads();
    }
    if (i < NNODES) g_off[i] = s[t] - v;          // exclusive
    if (t == SCAN_BLK - 1) g_part[blockIdx.x] = s[t];
}

__global__ __launch_bounds__(128) void k_scan2() {
    __shared__ int s[128];
    const int t = threadIdx.x;
    int v = (t < SCAN_NB) ? g_part[t] : 0;
    s[t] = v;
    __syncthreads();
    #pragma unroll
    for (int off = 1; off < 128; off <<= 1) {
        int add = (t >= off) ? s[t - off] : 0;
        __syncthreads();
        s[t] += add;
        __syncthreads();
    }
    if (t < SCAN_NB) g_part2[t] = s[t] - v;       // exclusive block offsets
}

__global__ void k_scan3() {
    int i = blockIdx.x * blockDim.x + threadIdx.x;
    if (i < NNODES) {
        int o = g_off[i] + g_part2[i >> 10];
        g_off[i] = o;
        g_cur[i] = o;
    }
}

__global__ void k_scatter(const int* __restrict__ ei) {
    int e = blockIdx.x * blockDim.x + threadIdx.x;
    if (e < NEDGES) {
        const int st = g_stride;
        int s = ei[(size_t)e * st];
        int d = ei[(size_t)NEDGES * st + (size_t)e * st];
        if ((unsigned)s < NNODES && (unsigned)d < NNODES) {
            int pos = atomicAdd(&g_cur[d], 1);
            g_esrc[pos] = s;
        }
    }
}

// ---------------------------------------------------------------------------
// Fused MLP: g_h2s[n] = dinv[n] * ( relu(X@W1+b1) @ W2 )[n]
// Register-blocked, float4 weight loads from SMEM.
// ---------------------------------------------------------------------------
__global__ __launch_bounds__(256) void k_mlp(
    const float* __restrict__ X, const float* __restrict__ W1,
    const float* __restrict__ b1, const float* __restrict__ W2)
{
    extern __shared__ float sm[];
    float* sW1 = sm;                    // IN_C*HID  = 8192 floats
    float* sW2 = sW1 + IN_C * HID;      // HID*OUT_C = 8192
    float* sb1 = sW2 + HID * OUT_C;     // 128
    float* sX  = sb1 + HID;             // NB*IN_C  = 2048
    float* sH  = sX + NB * IN_C;        // NB*HID   = 4096

    const int t = threadIdx.x;

    for (int i = t; i < IN_C * HID / 4; i += 256)
        ((float4*)sW1)[i] = ((const float4*)W1)[i];
    for (int i = t; i < HID * OUT_C / 4; i += 256)
        ((float4*)sW2)[i] = ((const float4*)W2)[i];
    if (t < HID) sb1[t] = b1[t];

    // Phase-1 mapping: 32 col-quads x 8 node-quads = 256 threads
    const int c4a = t & 31;           // col quad: cols c4a*4 .. +3 (of 128)
    const int nq  = t >> 5;           // node quad: nodes nq*4 .. +3 (of 32)
    // Phase-2 mapping: 16 col-quads x 16 node-pairs = 256 threads
    const int c4b = t & 15;           // col quad of 64
    const int np  = t >> 4;           // node pair: nodes np*2, np*2+1

    const int ntiles = NNODES / NB;   // 3125, exact
    for (int tile = blockIdx.x; tile < ntiles; tile += gridDim.x) {
        const int base = tile * NB;

        __syncthreads();
        for (int i = t; i < NB * IN_C / 4; i += 256)
            ((float4*)sX)[i] = ((const float4*)(X + (size_t)base * IN_C))[i];
        __syncthreads();

        // Phase 1: sH = relu(sX @ W1 + b1); 4 nodes x 4 cols per thread
        {
            float4 bias = *(const float4*)&sb1[c4a * 4];
            float4 a0 = bias, a1 = bias, a2 = bias, a3 = bias;
            const float* x0 = &sX[(nq * 4 + 0) * IN_C];
            const float* x1 = &sX[(nq * 4 + 1) * IN_C];
            const float* x2 = &sX[(nq * 4 + 2) * IN_C];
            const float* x3 = &sX[(nq * 4 + 3) * IN_C];
            #pragma unroll 8
            for (int k = 0; k < IN_C; k++) {
                float4 w = *(const float4*)&sW1[k * HID + c4a * 4];
                float v0 = x0[k], v1 = x1[k], v2 = x2[k], v3 = x3[k];
                a0.x = fmaf(v0, w.x, a0.x); a0.y = fmaf(v0, w.y, a0.y);
                a0.z = fmaf(v0, w.z, a0.z); a0.w = fmaf(v0, w.w, a0.w);
                a1.x = fmaf(v1, w.x, a1.x); a1.y = fmaf(v1, w.y, a1.y);
                a1.z = fmaf(v1, w.z, a1.z); a1.w = fmaf(v1, w.w, a1.w);
                a2.x = fmaf(v2, w.x, a2.x); a2.y = fmaf(v2, w.y, a2.y);
                a2.z = fmaf(v2, w.z, a2.z); a2.w = fmaf(v2, w.w, a2.w);
                a3.x = fmaf(v3, w.x, a3.x); a3.y = fmaf(v3, w.y, a3.y);
                a3.z = fmaf(v3, w.z, a3.z); a3.w = fmaf(v3, w.w, a3.w);
            }
            float4 z = make_float4(0.f, 0.f, 0.f, 0.f);
            float4 r0 = make_float4(fmaxf(a0.x,z.x), fmaxf(a0.y,z.y), fmaxf(a0.z,z.z), fmaxf(a0.w,z.w));
            float4 r1 = make_float4(fmaxf(a1.x,z.x), fmaxf(a1.y,z.y), fmaxf(a1.z,z.z), fmaxf(a1.w,z.w));
            float4 r2 = make_float4(fmaxf(a2.x,z.x), fmaxf(a2.y,z.y), fmaxf(a2.z,z.z), fmaxf(a2.w,z.w));
            float4 r3 = make_float4(fmaxf(a3.x,z.x), fmaxf(a3.y,z.y), fmaxf(a3.z,z.z), fmaxf(a3.w,z.w));
            *(float4*)&sH[(nq * 4 + 0) * HID + c4a * 4] = r0;
            *(float4*)&sH[(nq * 4 + 1) * HID + c4a * 4] = r1;
            *(float4*)&sH[(nq * 4 + 2) * HID + c4a * 4] = r2;
            *(float4*)&sH[(nq * 4 + 3) * HID + c4a * 4] = r3;
        }
        __syncthreads();

        // Phase 2: h2 = sH @ W2, scaled by dinv; 2 nodes x 4 cols per thread
        {
            float4 a0 = make_float4(0.f, 0.f, 0.f, 0.f);
            float4 a1 = a0;
            const float* h0 = &sH[(np * 2 + 0) * HID];
            const float* h1 = &sH[(np * 2 + 1) * HID];
            #pragma unroll 8
            for (int k = 0; k < HID; k++) {
                float4 w = *(const float4*)&sW2[k * OUT_C + c4b * 4];
                float v0 = h0[k], v1 = h1[k];
                a0.x = fmaf(v0, w.x, a0.x); a0.y = fmaf(v0, w.y, a0.y);
                a0.z = fmaf(v0, w.z, a0.z); a0.w = fmaf(v0, w.w, a0.w);
                a1.x = fmaf(v1, w.x, a1.x); a1.y = fmaf(v1, w.y, a1.y);
                a1.z = fmaf(v1, w.z, a1.z); a1.w = fmaf(v1, w.w, a1.w);
            }
            const int gn0 = base + np * 2, gn1 = gn0 + 1;
            float d0 = g_dinv[gn0], d1 = g_dinv[gn1];
            float4 o0 = make_float4(a0.x*d0, a0.y*d0, a0.z*d0, a0.w*d0);
            float4 o1 = make_float4(a1.x*d1, a1.y*d1, a1.z*d1, a1.w*d1);
            *(float4*)&g_h2s[(size_t)gn0 * OUT_C + c4b * 4] = o0;
            *(float4*)&g_h2s[(size_t)gn1 * OUT_C + c4b * 4] = o1;
        }
    }
}

// ---------------------------------------------------------------------------
// Pull aggregation: one warp per dst node, lane owns a float2 column chunk.
//   out[n] = dinv[n] * (h2s[n] + sum_{src->n} h2s[src]) + b2
// No atomics anywhere.
// ---------------------------------------------------------------------------
__global__ __launch_bounds__(256) void k_pull(
    const float* __restrict__ b2, float* __restrict__ out)
{
    const int warp = (blockIdx.x * blockDim.x + threadIdx.x) >> 5;
    const int lane = threadIdx.x & 31;
    if (warp >= NNODES) return;
    const int n = warp;
    const int c = lane * 2;

    const float2* __restrict__ tab = (const float2*)g_h2s;
    // self term (pre-scaled h2s row)
    float2 acc = tab[(size_t)n * (OUT_C / 2) + lane];

    const int beg = g_off[n];
    const int deg = g_degi[n];
    const int end = beg + deg;

    int i = beg;
    int s_next = (i < end) ? g_esrc[i] : 0;
    for (; i < end; i++) {
        const int s = s_next;
        if (i + 1 < end) s_next = g_esrc[i + 1];
        float2 v = tab[(size_t)s * (OUT_C / 2) + lane];
        acc.x += v.x;
        acc.y += v.y;
    }

    const float di = g_dinv[n];
    const float2 bb = ((const float2*)b2)[lane];
    float2 o;
    o.x = fmaf(di, acc.x, bb.x);
    o.y = fmaf(di, acc.y, bb.y);
    ((float2*)out)[(size_t)n * (OUT_C / 2) + lane] = o;
}

// ---------------------------------------------------------------------------
extern "C" void kernel_launch(void* const* d_in, const int* in_sizes, int n_in,
                              void* d_out, int out_size)
{
    const float* X   = (const float*)d_in[0];
    const int*   ei  = (const int*)d_in[1];   // width auto-detected on device
    const float* W1  = (const float*)d_in[2];
    const float* b1  = (const float*)d_in[3];
    const float* W2  = (const float*)d_in[4];
    const float* b2  = (const float*)d_in[5];
    float*       out = (float*)d_out;

    const int smem_bytes =
        (IN_C*HID + HID*OUT_C + HID + NB*IN_C + NB*HID) * 4;   // ~90 KB
    static int attr_done = 0;
    if (!attr_done) {
        cudaFuncSetAttribute(k_mlp, cudaFuncAttributeMaxDynamicSharedMemorySize, smem_bytes);
        attr_done = 1;
    }

    k_detect   <<<1, 32>>>(ei);
    k_deg_init <<<(NNODES + 255) / 256, 256>>>();
    k_deg_count<<<(NEDGES + 255) / 256, 256>>>(ei);
    k_dinv     <<<(NNODES + 255) / 256, 256>>>();
    k_scan1    <<<SCAN_NB, SCAN_BLK>>>();
    k_scan2    <<<1, 128>>>();
    k_scan3    <<<(NNODES + 255) / 256, 256>>>();
    k_scatter  <<<(NEDGES + 255) / 256, 256>>>(ei);
    k_mlp      <<<MLP_BLOCKS, 256, smem_bytes>>>(X, W1, b1, W2);
    k_pull     <<<(NNODES * 32 + 255) / 256, 256>>>(b2, out);
}

// round 4
// speedup vs baseline: 1.8522x; 1.0613x over previous
#include <cuda_runtime.h>
#include <cstdint>

#define NNODES 100000
#define NEDGES 1600000
#define IN_C 64
#define HID 128
#define OUT_C 64
#define NB 32            // nodes per MLP tile (100000 % 32 == 0)
#define MLP_BLOCKS 296
#define SCAN_BLK 1024
#define SCAN_NB ((NNODES + SCAN_BLK - 1) / SCAN_BLK)   // 98

// Scratch (static device arrays; heap alloc is forbidden)
__device__ __align__(16) float g_h2[(size_t)NNODES * OUT_C]; // unscaled h2, 25.6 MB
__device__ float g_dinv[NNODES];
__device__ int   g_degi[NNODES];     // in-degree (edges only)
__device__ int   g_off[NNODES];      // CSR offsets (exclusive scan of degi)
__device__ int   g_cur[NNODES];      // scatter cursors
__device__ int   g_esrc[NEDGES];     // CSR: src node per slot, grouped by dst
__device__ int   g_part[SCAN_NB];    // scan partials
__device__ int   g_part2[SCAN_NB];
__device__ int   g_stride;           // 1 = int32 edge_index, 2 = int64 (low word)

// ---------------------------------------------------------------------------
// Init: zero degree histogram; block 0 / warp 0 also detects index width.
// int64 ids < 2^31 have zero high words at int32 view positions 1,3,...,63.
// ---------------------------------------------------------------------------
__global__ void k_init(const int* __restrict__ ei) {
    int i = blockIdx.x * blockDim.x + threadIdx.x;
    if (i < NNODES) g_degi[i] = 0;
    if (blockIdx.x == 0 && threadIdx.x < 32) {
        int z = (ei[2 * threadIdx.x + 1] == 0);
        unsigned m = __ballot_sync(0xFFFFFFFFu, z);
        if (threadIdx.x == 0) g_stride = (m == 0xFFFFFFFFu) ? 2 : 1;
    }
}

__global__ void k_deg_count(const int* __restrict__ ei) {
    int e = blockIdx.x * blockDim.x + threadIdx.x;
    if (e < NEDGES) {
        const int st = g_stride;
        int d = ei[(size_t)NEDGES * st + (size_t)e * st];
        if ((unsigned)d < NNODES) atomicAdd(&g_degi[d], 1);
    }
}

// ---------------------------------------------------------------------------
// Block scan (warp-shuffle) of g_degi -> g_off (exclusive); also computes dinv.
// ---------------------------------------------------------------------------
__global__ __launch_bounds__(SCAN_BLK) void k_scan1() {
    __shared__ int wsum[32];
    const int t = threadIdx.x;
    const int i = blockIdx.x * SCAN_BLK + t;
    const int v = (i < NNODES) ? g_degi[i] : 0;
    if (i < NNODES) g_dinv[i] = rsqrtf((float)(v + 1));   // +1 self-loop

    int x = v;                                  // inclusive within warp
    #pragma unroll
    for (int o = 1; o < 32; o <<= 1) {
        int y = __shfl_up_sync(0xFFFFFFFFu, x, o);
        if ((t & 31) >= o) x += y;
    }
    if ((t & 31) == 31) wsum[t >> 5] = x;
    __syncthreads();
    if (t < 32) {
        int w = wsum[t];
        int xx = w;
        #pragma unroll
        for (int o = 1; o < 32; o <<= 1) {
            int y = __shfl_up_sync(0xFFFFFFFFu, xx, o);
            if (t >= o) xx += y;
        }
        wsum[t] = xx - w;                       // exclusive warp offsets
        if (t == 31) g_part[blockIdx.x] = xx;   // block total
    }
    __syncthreads();
    if (i < NNODES) g_off[i] = x - v + wsum[t >> 5];
}

__global__ __launch_bounds__(128) void k_scan2() {
    __shared__ int s[128];
    const int t = threadIdx.x;
    int v = (t < SCAN_NB) ? g_part[t] : 0;
    s[t] = v;
    __syncthreads();
    #pragma unroll
    for (int off = 1; off < 128; off <<= 1) {
        int add = (t >= off) ? s[t - off] : 0;
        __syncthreads();
        s[t] += add;
        __syncthreads();
    }
    if (t < SCAN_NB) g_part2[t] = s[t] - v;
}

__global__ void k_scan3() {
    int i = blockIdx.x * blockDim.x + threadIdx.x;
    if (i < NNODES) {
        int o = g_off[i] + g_part2[i >> 10];
        g_off[i] = o;
        g_cur[i] = o;
    }
}

__global__ void k_scatter(const int* __restrict__ ei) {
    int e = blockIdx.x * blockDim.x + threadIdx.x;
    if (e < NEDGES) {
        const int st = g_stride;
        int s = ei[(size_t)e * st];
        int d = ei[(size_t)NEDGES * st + (size_t)e * st];
        if ((unsigned)s < NNODES && (unsigned)d < NNODES) {
            int pos = atomicAdd(&g_cur[d], 1);
            g_esrc[pos] = s;
        }
    }
}

// ---------------------------------------------------------------------------
// Fused MLP: g_h2[n] = relu(X@W1+b1)[n] @ W2   (UNSCALED -> no dep on dinv)
// ---------------------------------------------------------------------------
__global__ __launch_bounds__(256) void k_mlp(
    const float* __restrict__ X, const float* __restrict__ W1,
    const float* __restrict__ b1, const float* __restrict__ W2)
{
    extern __shared__ float sm[];
    float* sW1 = sm;                    // IN_C*HID  = 8192 floats
    float* sW2 = sW1 + IN_C * HID;      // HID*OUT_C = 8192
    float* sb1 = sW2 + HID * OUT_C;     // 128
    float* sX  = sb1 + HID;             // NB*IN_C  = 2048
    float* sH  = sX + NB * IN_C;        // NB*HID   = 4096

    const int t = threadIdx.x;

    for (int i = t; i < IN_C * HID / 4; i += 256)
        ((float4*)sW1)[i] = ((const float4*)W1)[i];
    for (int i = t; i < HID * OUT_C / 4; i += 256)
        ((float4*)sW2)[i] = ((const float4*)W2)[i];
    if (t < HID) sb1[t] = b1[t];

    const int c4a = t & 31;           // phase-1 col quad (of 128)
    const int nq  = t >> 5;           // phase-1 node quad (of 32)
    const int c4b = t & 15;           // phase-2 col quad (of 64)
    const int np  = t >> 4;           // phase-2 node pair

    const int ntiles = NNODES / NB;   // 3125, exact
    for (int tile = blockIdx.x; tile < ntiles; tile += gridDim.x) {
        const int base = tile * NB;

        __syncthreads();
        for (int i = t; i < NB * IN_C / 4; i += 256)
            ((float4*)sX)[i] = ((const float4*)(X + (size_t)base * IN_C))[i];
        __syncthreads();

        // Phase 1: sH = relu(sX @ W1 + b1); 4 nodes x 4 cols per thread
        {
            float4 bias = *(const float4*)&sb1[c4a * 4];
            float4 a0 = bias, a1 = bias, a2 = bias, a3 = bias;
            const float* x0 = &sX[(nq * 4 + 0) * IN_C];
            const float* x1 = &sX[(nq * 4 + 1) * IN_C];
            const float* x2 = &sX[(nq * 4 + 2) * IN_C];
            const float* x3 = &sX[(nq * 4 + 3) * IN_C];
            #pragma unroll 8
            for (int k = 0; k < IN_C; k++) {
                float4 w = *(const float4*)&sW1[k * HID + c4a * 4];
                float v0 = x0[k], v1 = x1[k], v2 = x2[k], v3 = x3[k];
                a0.x = fmaf(v0, w.x, a0.x); a0.y = fmaf(v0, w.y, a0.y);
                a0.z = fmaf(v0, w.z, a0.z); a0.w = fmaf(v0, w.w, a0.w);
                a1.x = fmaf(v1, w.x, a1.x); a1.y = fmaf(v1, w.y, a1.y);
                a1.z = fmaf(v1, w.z, a1.z); a1.w = fmaf(v1, w.w, a1.w);
                a2.x = fmaf(v2, w.x, a2.x); a2.y = fmaf(v2, w.y, a2.y);
                a2.z = fmaf(v2, w.z, a2.z); a2.w = fmaf(v2, w.w, a2.w);
                a3.x = fmaf(v3, w.x, a3.x); a3.y = fmaf(v3, w.y, a3.y);
                a3.z = fmaf(v3, w.z, a3.z); a3.w = fmaf(v3, w.w, a3.w);
            }
            *(float4*)&sH[(nq*4+0)*HID + c4a*4] = make_float4(fmaxf(a0.x,0.f),fmaxf(a0.y,0.f),fmaxf(a0.z,0.f),fmaxf(a0.w,0.f));
            *(float4*)&sH[(nq*4+1)*HID + c4a*4] = make_float4(fmaxf(a1.x,0.f),fmaxf(a1.y,0.f),fmaxf(a1.z,0.f),fmaxf(a1.w,0.f));
            *(float4*)&sH[(nq*4+2)*HID + c4a*4] = make_float4(fmaxf(a2.x,0.f),fmaxf(a2.y,0.f),fmaxf(a2.z,0.f),fmaxf(a2.w,0.f));
            *(float4*)&sH[(nq*4+3)*HID + c4a*4] = make_float4(fmaxf(a3.x,0.f),fmaxf(a3.y,0.f),fmaxf(a3.z,0.f),fmaxf(a3.w,0.f));
        }
        __syncthreads();

        // Phase 2: h2 = sH @ W2; 2 nodes x 4 cols per thread
        {
            float4 a0 = make_float4(0.f, 0.f, 0.f, 0.f);
            float4 a1 = a0;
            const float* h0 = &sH[(np * 2 + 0) * HID];
            const float* h1 = &sH[(np * 2 + 1) * HID];
            #pragma unroll 8
            for (int k = 0; k < HID; k++) {
                float4 w = *(const float4*)&sW2[k * OUT_C + c4b * 4];
                float v0 = h0[k], v1 = h1[k];
                a0.x = fmaf(v0, w.x, a0.x); a0.y = fmaf(v0, w.y, a0.y);
                a0.z = fmaf(v0, w.z, a0.z); a0.w = fmaf(v0, w.w, a0.w);
                a1.x = fmaf(v1, w.x, a1.x); a1.y = fmaf(v1, w.y, a1.y);
                a1.z = fmaf(v1, w.z, a1.z); a1.w = fmaf(v1, w.w, a1.w);
            }
            const int gn0 = base + np * 2, gn1 = gn0 + 1;
            *(float4*)&g_h2[(size_t)gn0 * OUT_C + c4b * 4] = a0;
            *(float4*)&g_h2[(size_t)gn1 * OUT_C + c4b * 4] = a1;
        }
    }
}

// ---------------------------------------------------------------------------
// Pull aggregation: one warp per dst node, lane owns a float2 column chunk.
//   out[n] = dinv[n] * ( dinv[n]*h2[n] + sum_{s->n} dinv[s]*h2[s] ) + b2
// No atomics anywhere.
// ---------------------------------------------------------------------------
__global__ __launch_bounds__(256) void k_pull(
    const float* __restrict__ b2, float* __restrict__ out)
{
    const int warp = (blockIdx.x * blockDim.x + threadIdx.x) >> 5;
    const int lane = threadIdx.x & 31;
    if (warp >= NNODES) return;
    const int n = warp;

    const float2* __restrict__ tab = (const float2*)g_h2;
    const float din = g_dinv[n];

    // self term: dinv[n] * h2[n]
    float2 self = tab[(size_t)n * (OUT_C / 2) + lane];
    float2 acc;
    acc.x = din * self.x;
    acc.y = din * self.y;

    const int beg = g_off[n];
    const int end = beg + g_degi[n];

    int i = beg;
    int s_next = (i < end) ? g_esrc[i] : 0;
    float ds_next = (i < end) ? g_dinv[s_next] : 0.f;
    for (; i < end; i++) {
        const int s = s_next;
        const float ds = ds_next;
        if (i + 1 < end) {
            s_next = g_esrc[i + 1];
            ds_next = g_dinv[s_next];
        }
        float2 v = tab[(size_t)s * (OUT_C / 2) + lane];
        acc.x = fmaf(ds, v.x, acc.x);
        acc.y = fmaf(ds, v.y, acc.y);
    }

    const float2 bb = ((const float2*)b2)[lane];
    float2 o;
    o.x = fmaf(din, acc.x, bb.x);
    o.y = fmaf(din, acc.y, bb.y);
    ((float2*)out)[(size_t)n * (OUT_C / 2) + lane] = o;
}

// ---------------------------------------------------------------------------
extern "C" void kernel_launch(void* const* d_in, const int* in_sizes, int n_in,
                              void* d_out, int out_size)
{
    const float* X   = (const float*)d_in[0];
    const int*   ei  = (const int*)d_in[1];   // width auto-detected on device
    const float* W1  = (const float*)d_in[2];
    const float* b1  = (const float*)d_in[3];
    const float* W2  = (const float*)d_in[4];
    const float* b2  = (const float*)d_in[5];
    float*       out = (float*)d_out;

    const int smem_bytes =
        (IN_C*HID + HID*OUT_C + HID + NB*IN_C + NB*HID) * 4;   // ~90 KB

    static cudaStream_t s1;
    static cudaEvent_t evRoot, evMlp;
    static int init_done = 0;
    if (!init_done) {
        cudaFuncSetAttribute(k_mlp, cudaFuncAttributeMaxDynamicSharedMemorySize, smem_bytes);
        cudaStreamCreateWithFlags(&s1, cudaStreamNonBlocking);
        cudaEventCreateWithFlags(&evRoot, cudaEventDisableTiming);
        cudaEventCreateWithFlags(&evMlp, cudaEventDisableTiming);
        init_done = 1;
    }

    // Fork: k_mlp is independent of the edge/CSR chain.
    cudaEventRecord(evRoot, 0);
    cudaStreamWaitEvent(s1, evRoot, 0);
    k_mlp<<<MLP_BLOCKS, 256, smem_bytes, s1>>>(X, W1, b1, W2);
    cudaEventRecord(evMlp, s1);

    // Edge/CSR chain on the capture (legacy) stream.
    k_init     <<<(NNODES + 255) / 256, 256>>>(ei);
    k_deg_count<<<(NEDGES + 255) / 256, 256>>>(ei);
    k_scan1    <<<SCAN_NB, SCAN_BLK>>>();
    k_scan2    <<<1, 128>>>();
    k_scan3    <<<(NNODES + 255) / 256, 256>>>();
    k_scatter  <<<(NEDGES + 255) / 256, 256>>>(ei);

    // Join, then pull.
    cudaStreamWaitEvent(0, evMlp, 0);
    k_pull     <<<(NNODES * 32 + 255) / 256, 256>>>(b2, out);
}

// round 5
// speedup vs baseline: 2.0216x; 1.0914x over previous
#include <cuda_runtime.h>
#include <cstdint>

#define NNODES 100000
#define NEDGES 1600000
#define IN_C 64
#define HID 128
#define OUT_C 64
#define NB 32            // nodes per MLP tile (100000 % 32 == 0)
#define MLP_BLOCKS 296
#define SCAN_BLK 1024
#define SCAN_NB ((NNODES + SCAN_BLK - 1) / SCAN_BLK)   // 98 blocks, all co-resident

// Scratch (static device arrays; heap alloc is forbidden)
__device__ __align__(16) float g_h2[(size_t)NNODES * OUT_C]; // unscaled h2, 25.6 MB
__device__ float g_dinv[NNODES];
__device__ int   g_degi[NNODES];     // in-degree (edges only); memset to 0 per call
__device__ int   g_off[NNODES];      // CSR offsets; scatter bumps them to 'end'
__device__ int   g_esrc[NEDGES];     // CSR: src node per slot, grouped by dst
__device__ unsigned long long g_scanstate[SCAN_NB];  // lookback states; memset per call

// ---------------------------------------------------------------------------
// Per-block index-width detection: int64 ids < 2^31 have zero high words at
// int32 view positions 1,3,...,63. Genuine int32 ids are uniform in [0,1e5).
// ---------------------------------------------------------------------------
__device__ __forceinline__ int detect_stride(const int* __restrict__ ei, int* s_st) {
    if (threadIdx.x < 32) {
        int z = (ei[2 * threadIdx.x + 1] == 0);
        unsigned m = __ballot_sync(0xFFFFFFFFu, z);
        if (threadIdx.x == 0) *s_st = (m == 0xFFFFFFFFu) ? 2 : 1;
    }
    __syncthreads();
    return *s_st;
}

// ---------------------------------------------------------------------------
// Degree histogram
// ---------------------------------------------------------------------------
__global__ __launch_bounds__(256) void k_deg_count(const int* __restrict__ ei) {
    __shared__ int s_st;
    const int st = detect_stride(ei, &s_st);
    int e = blockIdx.x * blockDim.x + threadIdx.x;
    if (e < NEDGES) {
        int d = ei[(size_t)NEDGES * st + (size_t)e * st];
        if ((unsigned)d < NNODES) atomicAdd(&g_degi[d], 1);
    }
}

// ---------------------------------------------------------------------------
// Single-pass exclusive scan of g_degi -> g_off with decoupled lookback.
// Also computes g_dinv. All SCAN_NB blocks are co-resident -> spin is safe.
// State packing: hi 32 = flag (0=none, 1=aggregate, 2=inclusive prefix), lo 32 = value.
// ---------------------------------------------------------------------------
__global__ __launch_bounds__(SCAN_BLK) void k_scan() {
    __shared__ int wsum[32];
    __shared__ int s_total, s_prefix;
    const int t = threadIdx.x;
    const int bid = blockIdx.x;
    const int i = bid * SCAN_BLK + t;
    const int v = (i < NNODES) ? g_degi[i] : 0;
    if (i < NNODES) g_dinv[i] = rsqrtf((float)(v + 1));   // +1 self-loop

    // warp inclusive scan
    int x = v;
    #pragma unroll
    for (int o = 1; o < 32; o <<= 1) {
        int y = __shfl_up_sync(0xFFFFFFFFu, x, o);
        if ((t & 31) >= o) x += y;
    }
    if ((t & 31) == 31) wsum[t >> 5] = x;
    __syncthreads();
    if (t < 32) {
        int w = wsum[t];
        int xx = w;
        #pragma unroll
        for (int o = 1; o < 32; o <<= 1) {
            int y = __shfl_up_sync(0xFFFFFFFFu, xx, o);
            if (t >= o) xx += y;
        }
        wsum[t] = xx - w;                 // exclusive warp offsets
        if (t == 31) s_total = xx;        // block total
    }
    __syncthreads();

    // publish aggregate (or prefix for block 0)
    if (t == 0) {
        unsigned long long flag = (bid == 0) ? 2ULL : 1ULL;
        __threadfence();
        *(volatile unsigned long long*)&g_scanstate[bid] =
            (flag << 32) | (unsigned)s_total;
        if (bid == 0) s_prefix = 0;
    }

    // warp-collective lookback
    if (bid > 0 && t < 32) {
        int running = 0;
        int base = bid - 1;
        for (;;) {
            int j = base - t;
            unsigned long long s;
            if (j >= 0) {
                do { s = *(volatile unsigned long long*)&g_scanstate[j]; }
                while ((s >> 32) == 0);
            } else {
                s = (2ULL << 32);         // virtual prefix 0 before block 0
            }
            int flag = (int)(s >> 32);
            int val  = (int)(s & 0xFFFFFFFFu);
            unsigned pmask = __ballot_sync(0xFFFFFFFFu, flag == 2);
            if (pmask) {
                int stop = __ffs(pmask) - 1;       // nearest prefix
                int contrib = (t <= stop) ? val : 0;
                #pragma unroll
                for (int o = 16; o >= 1; o >>= 1)
                    contrib += __shfl_down_sync(0xFFFFFFFFu, contrib, o);
                running += __shfl_sync(0xFFFFFFFFu, contrib, 0);
                break;
            } else {
                int contrib = val;                  // all aggregates
                #pragma unroll
                for (int o = 16; o >= 1; o >>= 1)
                    contrib += __shfl_down_sync(0xFFFFFFFFu, contrib, o);
                running += __shfl_sync(0xFFFFFFFFu, contrib, 0);
                base -= 32;
            }
        }
        if (t == 0) {
            __threadfence();
            *(volatile unsigned long long*)&g_scanstate[bid] =
                (2ULL << 32) | (unsigned)(running + s_total);
            s_prefix = running;
        }
    }
    __syncthreads();

    if (i < NNODES) g_off[i] = (x - v + wsum[t >> 5]) + s_prefix;
}

// ---------------------------------------------------------------------------
// Scatter edges into CSR slots. Bumps g_off in place: afterwards g_off[n] = end.
// ---------------------------------------------------------------------------
__global__ __launch_bounds__(256) void k_scatter(const int* __restrict__ ei) {
    __shared__ int s_st;
    const int st = detect_stride(ei, &s_st);
    int e = blockIdx.x * blockDim.x + threadIdx.x;
    if (e < NEDGES) {
        int s = ei[(size_t)e * st];
        int d = ei[(size_t)NEDGES * st + (size_t)e * st];
        if ((unsigned)s < NNODES && (unsigned)d < NNODES) {
            int pos = atomicAdd(&g_off[d], 1);
            g_esrc[pos] = s;
        }
    }
}

// ---------------------------------------------------------------------------
// Fused MLP: g_h2[n] = relu(X@W1+b1)[n] @ W2   (independent of edge chain)
// ---------------------------------------------------------------------------
__global__ __launch_bounds__(256) void k_mlp(
    const float* __restrict__ X, const float* __restrict__ W1,
    const float* __restrict__ b1, const float* __restrict__ W2)
{
    extern __shared__ float sm[];
    float* sW1 = sm;                    // IN_C*HID  = 8192 floats
    float* sW2 = sW1 + IN_C * HID;      // HID*OUT_C = 8192
    float* sb1 = sW2 + HID * OUT_C;     // 128
    float* sX  = sb1 + HID;             // NB*IN_C  = 2048
    float* sH  = sX + NB * IN_C;        // NB*HID   = 4096

    const int t = threadIdx.x;

    for (int i = t; i < IN_C * HID / 4; i += 256)
        ((float4*)sW1)[i] = ((const float4*)W1)[i];
    for (int i = t; i < HID * OUT_C / 4; i += 256)
        ((float4*)sW2)[i] = ((const float4*)W2)[i];
    if (t < HID) sb1[t] = b1[t];

    const int c4a = t & 31;           // phase-1 col quad (of 128)
    const int nq  = t >> 5;           // phase-1 node quad (of 32)
    const int c4b = t & 15;           // phase-2 col quad (of 64)
    const int np  = t >> 4;           // phase-2 node pair

    const int ntiles = NNODES / NB;   // 3125, exact
    for (int tile = blockIdx.x; tile < ntiles; tile += gridDim.x) {
        const int base = tile * NB;

        __syncthreads();
        for (int i = t; i < NB * IN_C / 4; i += 256)
            ((float4*)sX)[i] = ((const float4*)(X + (size_t)base * IN_C))[i];
        __syncthreads();

        // Phase 1: sH = relu(sX @ W1 + b1); 4 nodes x 4 cols per thread
        {
            float4 bias = *(const float4*)&sb1[c4a * 4];
            float4 a0 = bias, a1 = bias, a2 = bias, a3 = bias;
            const float* x0 = &sX[(nq * 4 + 0) * IN_C];
            const float* x1 = &sX[(nq * 4 + 1) * IN_C];
            const float* x2 = &sX[(nq * 4 + 2) * IN_C];
            const float* x3 = &sX[(nq * 4 + 3) * IN_C];
            #pragma unroll 8
            for (int k = 0; k < IN_C; k++) {
                float4 w = *(const float4*)&sW1[k * HID + c4a * 4];
                float v0 = x0[k], v1 = x1[k], v2 = x2[k], v3 = x3[k];
                a0.x = fmaf(v0, w.x, a0.x); a0.y = fmaf(v0, w.y, a0.y);
                a0.z = fmaf(v0, w.z, a0.z); a0.w = fmaf(v0, w.w, a0.w);
                a1.x = fmaf(v1, w.x, a1.x); a1.y = fmaf(v1, w.y, a1.y);
                a1.z = fmaf(v1, w.z, a1.z); a1.w = fmaf(v1, w.w, a1.w);
                a2.x = fmaf(v2, w.x, a2.x); a2.y = fmaf(v2, w.y, a2.y);
                a2.z = fmaf(v2, w.z, a2.z); a2.w = fmaf(v2, w.w, a2.w);
                a3.x = fmaf(v3, w.x, a3.x); a3.y = fmaf(v3, w.y, a3.y);
                a3.z = fmaf(v3, w.z, a3.z); a3.w = fmaf(v3, w.w, a3.w);
            }
            *(float4*)&sH[(nq*4+0)*HID + c4a*4] = make_float4(fmaxf(a0.x,0.f),fmaxf(a0.y,0.f),fmaxf(a0.z,0.f),fmaxf(a0.w,0.f));
            *(float4*)&sH[(nq*4+1)*HID + c4a*4] = make_float4(fmaxf(a1.x,0.f),fmaxf(a1.y,0.f),fmaxf(a1.z,0.f),fmaxf(a1.w,0.f));
            *(float4*)&sH[(nq*4+2)*HID + c4a*4] = make_float4(fmaxf(a2.x,0.f),fmaxf(a2.y,0.f),fmaxf(a2.z,0.f),fmaxf(a2.w,0.f));
            *(float4*)&sH[(nq*4+3)*HID + c4a*4] = make_float4(fmaxf(a3.x,0.f),fmaxf(a3.y,0.f),fmaxf(a3.z,0.f),fmaxf(a3.w,0.f));
        }
        __syncthreads();

        // Phase 2: h2 = sH @ W2; 2 nodes x 4 cols per thread
        {
            float4 a0 = make_float4(0.f, 0.f, 0.f, 0.f);
            float4 a1 = a0;
            const float* h0 = &sH[(np * 2 + 0) * HID];
            const float* h1 = &sH[(np * 2 + 1) * HID];
            #pragma unroll 8
            for (int k = 0; k < HID; k++) {
                float4 w = *(const float4*)&sW2[k * OUT_C + c4b * 4];
                float v0 = h0[k], v1 = h1[k];
                a0.x = fmaf(v0, w.x, a0.x); a0.y = fmaf(v0, w.y, a0.y);
                a0.z = fmaf(v0, w.z, a0.z); a0.w = fmaf(v0, w.w, a0.w);
                a1.x = fmaf(v1, w.x, a1.x); a1.y = fmaf(v1, w.y, a1.y);
                a1.z = fmaf(v1, w.z, a1.z); a1.w = fmaf(v1, w.w, a1.w);
            }
            const int gn0 = base + np * 2, gn1 = gn0 + 1;
            *(float4*)&g_h2[(size_t)gn0 * OUT_C + c4b * 4] = a0;
            *(float4*)&g_h2[(size_t)gn1 * OUT_C + c4b * 4] = a1;
        }
    }
}

// ---------------------------------------------------------------------------
// Pull aggregation: one warp per dst node, lane owns a float2 column chunk.
//   out[n] = dinv[n] * ( dinv[n]*h2[n] + sum_{s->n} dinv[s]*h2[s] ) + b2
// 2-edge unroll keeps two independent gathers in flight.
// ---------------------------------------------------------------------------
__global__ __launch_bounds__(256) void k_pull(
    const float* __restrict__ b2, float* __restrict__ out)
{
    const int warp = (blockIdx.x * blockDim.x + threadIdx.x) >> 5;
    const int lane = threadIdx.x & 31;
    if (warp >= NNODES) return;
    const int n = warp;

    const float2* __restrict__ tab = (const float2*)g_h2;
    const float din = g_dinv[n];

    float2 self = tab[(size_t)n * (OUT_C / 2) + lane];
    float2 acc;
    acc.x = din * self.x;
    acc.y = din * self.y;

    const int deg = g_degi[n];
    const int end = g_off[n];           // scatter bumped off to 'end'
    const int beg = end - deg;

    int i = beg;
    for (; i + 1 < end; i += 2) {
        const int s0 = __ldg(&g_esrc[i]);
        const int s1 = __ldg(&g_esrc[i + 1]);
        const float d0 = g_dinv[s0];
        const float d1 = g_dinv[s1];
        float2 v0 = tab[(size_t)s0 * (OUT_C / 2) + lane];
        float2 v1 = tab[(size_t)s1 * (OUT_C / 2) + lane];
        acc.x = fmaf(d0, v0.x, acc.x);
        acc.y = fmaf(d0, v0.y, acc.y);
        acc.x = fmaf(d1, v1.x, acc.x);
        acc.y = fmaf(d1, v1.y, acc.y);
    }
    if (i < end) {
        const int s = __ldg(&g_esrc[i]);
        const float ds = g_dinv[s];
        float2 v = tab[(size_t)s * (OUT_C / 2) + lane];
        acc.x = fmaf(ds, v.x, acc.x);
        acc.y = fmaf(ds, v.y, acc.y);
    }

    const float2 bb = ((const float2*)b2)[lane];
    float2 o;
    o.x = fmaf(din, acc.x, bb.x);
    o.y = fmaf(din, acc.y, bb.y);
    ((float2*)out)[(size_t)n * (OUT_C / 2) + lane] = o;
}

// ---------------------------------------------------------------------------
extern "C" void kernel_launch(void* const* d_in, const int* in_sizes, int n_in,
                              void* d_out, int out_size)
{
    const float* X   = (const float*)d_in[0];
    const int*   ei  = (const int*)d_in[1];   // width auto-detected per block
    const float* W1  = (const float*)d_in[2];
    const float* b1  = (const float*)d_in[3];
    const float* W2  = (const float*)d_in[4];
    const float* b2  = (const float*)d_in[5];
    float*       out = (float*)d_out;

    const int smem_bytes =
        (IN_C*HID + HID*OUT_C + HID + NB*IN_C + NB*HID) * 4;   // ~90 KB

    static cudaStream_t s1;
    static cudaEvent_t evRoot, evMlp;
    static void *p_degi, *p_state;
    static int init_done = 0;
    if (!init_done) {
        cudaFuncSetAttribute(k_mlp, cudaFuncAttributeMaxDynamicSharedMemorySize, smem_bytes);
        cudaStreamCreateWithFlags(&s1, cudaStreamNonBlocking);
        cudaEventCreateWithFlags(&evRoot, cudaEventDisableTiming);
        cudaEventCreateWithFlags(&evMlp, cudaEventDisableTiming);
        cudaGetSymbolAddress(&p_degi, g_degi);
        cudaGetSymbolAddress(&p_state, g_scanstate);
        init_done = 1;
    }

    cudaEventRecord(evRoot, 0);

    // Critical chain on the capture (legacy) stream — starts immediately.
    cudaMemsetAsync(p_degi, 0, NNODES * sizeof(int), 0);
    cudaMemsetAsync(p_state, 0, SCAN_NB * sizeof(unsigned long long), 0);
    k_deg_count<<<(NEDGES + 255) / 256, 256>>>(ei);
    k_scan     <<<SCAN_NB, SCAN_BLK>>>();
    k_scatter  <<<(NEDGES + 255) / 256, 256>>>(ei);

    // Fork: MLP depends only on the root.
    cudaStreamWaitEvent(s1, evRoot, 0);
    k_mlp<<<MLP_BLOCKS, 256, smem_bytes, s1>>>(X, W1, b1, W2);
    cudaEventRecord(evMlp, s1);

    // Join, then pull.
    cudaStreamWaitEvent(0, evMlp, 0);
    k_pull     <<<(NNODES * 32 + 255) / 256, 256>>>(b2, out);
}